// round 11
// baseline (speedup 1.0000x reference)
#include <cuda_runtime.h>
#include <cstdint>

#define NTOT 500000
#define CT 64
#define THREADS 512
#define NTILES ((NTOT + CT - 1) / CT)   // 7813

// smem layout (float offsets)
#define OFF_WT 0        // W^T: [128 n][128 k], word k ^ ((n&7)<<4)   (512B rows)
#define OFF_WG 16384
#define OFF_X  32768    // X:   [64 m][128 k], word k ^ ((m&7)<<4)    (512B rows)
#define OFF_M  40960    // mask:[128 b][64 k] int, word k ^ ((b&7)<<2) (256B rows)
#define OFF_Y  49152    // Y:   [64 m][128 n], word n ^ (((m&3)<<3)|((m&4)>>2))
#define SMEM_FLOATS 57344
#define SMEM_BYTES (SMEM_FLOATS * 4)    // 229376 <= 232448

__device__ __forceinline__ float cvt_tf32_f(float x) {
    uint32_t u; asm("cvt.rna.tf32.f32 %0, %1;" : "=r"(u) : "f"(x));
    return __uint_as_float(u);
}
__device__ __forceinline__ void mma8(float* c,
                                     uint32_t a0, uint32_t a1, uint32_t a2, uint32_t a3,
                                     uint32_t b0, uint32_t b1) {
    asm volatile(
        "mma.sync.aligned.m16n8k8.row.col.f32.tf32.tf32.f32 "
        "{%0,%1,%2,%3}, {%4,%5,%6,%7}, {%8,%9}, {%0,%1,%2,%3};"
        : "+f"(c[0]), "+f"(c[1]), "+f"(c[2]), "+f"(c[3])
        : "r"(a0), "r"(a1), "r"(a2), "r"(a3), "r"(b0), "r"(b1));
}
__device__ __forceinline__ void cp16(uint32_t saddr, const void* g, int szbytes) {
    asm volatile("cp.async.cg.shared.global [%0], [%1], 16, %2;"
                 :: "r"(saddr), "l"(g), "r"(szbytes));
}
#define CP_COMMIT() asm volatile("cp.async.commit_group;")
#define CP_WAIT0()  asm volatile("cp.async.wait_group 0;")
#define LDS128(r0,r1,r2,r3,a) asm volatile("ld.shared.v4.u32 {%0,%1,%2,%3}, [%4];" \
    : "=r"(r0), "=r"(r1), "=r"(r2), "=r"(r3) : "r"(a))

extern "C" __global__ void zero_out_kernel(float* __restrict__ out) {
    int i = blockIdx.x * blockDim.x + threadIdx.x;
    if (i < 128 * 128) out[i] = 0.0f;
}

// ---- phase A block: real-k window [16*ks2, +16) = 2 relabeled k-steps.
//      8 LDS.128 -> 32 MMAs. Slot relabel (shared by A/B frags):
//      sub0: kappa=tg -> k=16ks2+4tg, kappa=tg+4 -> +1; sub1: +2, +3.
#define ASTEP2(ks2) do {                                                        \
    const uint32_t koff = ((uint32_t)(((ks2) ^ gid) << 6)) + ((uint32_t)tg << 4); \
    uint32_t x0[4], x1[4], x2[4], x3[4];                                        \
    LDS128(x0[0],x0[1],x0[2],x0[3], xbase + koff);                              \
    LDS128(x1[0],x1[1],x1[2],x1[3], xbase + (8 << 9) + koff);                   \
    LDS128(x2[0],x2[1],x2[2],x2[3], xbase + (16 << 9) + koff);                  \
    LDS128(x3[0],x3[1],x3[2],x3[3], xbase + (24 << 9) + koff);                  \
    _Pragma("unroll")                                                           \
    for (int j = 0; j < 2; j++) {                                               \
        uint32_t d[4], g[4];                                                    \
        LDS128(d[0],d[1],d[2],d[3], wtbase + (j << 12) + koff);                 \
        LDS128(g[0],g[1],g[2],g[3], wgbase + (j << 12) + koff);                 \
        mma8(aD[0][j], x0[0],x1[0],x0[1],x1[1], d[0],d[1]);                     \
        mma8(aD[1][j], x2[0],x3[0],x2[1],x3[1], d[0],d[1]);                     \
        mma8(aG[0][j], x0[0],x1[0],x0[1],x1[1], g[0],g[1]);                     \
        mma8(aG[1][j], x2[0],x3[0],x2[1],x3[1], g[0],g[1]);                     \
        mma8(aD[0][j], x0[2],x1[2],x0[3],x1[3], d[2],d[3]);                     \
        mma8(aD[1][j], x2[2],x3[2],x2[3],x3[3], d[2],d[3]);                     \
        mma8(aG[0][j], x0[2],x1[2],x0[3],x1[3], g[2],g[3]);                     \
        mma8(aG[1][j], x2[2],x3[2],x2[3],x3[3], g[2],g[3]);                     \
    }                                                                           \
} while (0)

// ---- phase B k-step (R7, unchanged): LDS.32, conflict-free ----
#define BSTEP(ks) do {                                                          \
    const int kk = (ks) * 8 + tg;                                               \
    uint32_t m0 = __float_as_uint((float)sM[(brow0 << 6)        + (kk ^ msw)]); \
    uint32_t m1 = __float_as_uint((float)sM[((brow0 + 8) << 6)  + (kk ^ msw)]); \
    uint32_t m2 = __float_as_uint((float)sM[(brow0 << 6)        + ((kk + 4) ^ msw)]); \
    uint32_t m3 = __float_as_uint((float)sM[((brow0 + 8) << 6)  + ((kk + 4) ^ msw)]); \
    uint32_t m4 = __float_as_uint((float)sM[((brow0 + 16) << 6) + (kk ^ msw)]); \
    uint32_t m5 = __float_as_uint((float)sM[((brow0 + 24) << 6) + (kk ^ msw)]); \
    uint32_t m6 = __float_as_uint((float)sM[((brow0 + 16) << 6) + ((kk + 4) ^ msw)]); \
    uint32_t m7 = __float_as_uint((float)sM[((brow0 + 24) << 6) + ((kk + 4) ^ msw)]); \
    const int yb0 = kk << 7;                                                    \
    const int yb1 = (kk + 4) << 7;                                              \
    const int ysw0 = tg << 3;                                                   \
    const int ysw1 = (tg << 3) | 1;                                             \
    _Pragma("unroll")                                                           \
    for (int j = 0; j < 4; j++) {                                               \
        const int d = (pd << 5) + 8 * j + gid;                                  \
        uint32_t y0 = __float_as_uint(sY[yb0 + (d ^ ysw0)]);                    \
        uint32_t y1 = __float_as_uint(sY[yb1 + (d ^ ysw1)]);                    \
        mma8(pc[0][j], m0, m1, m2, m3, y0, y1);                                 \
        mma8(pc[1][j], m4, m5, m6, m7, y0, y1);                                 \
    }                                                                           \
} while (0)

#define ISSUE_X(tile) do {                                                      \
    const int nn0 = (tile) * CT;                                                \
    _Pragma("unroll")                                                           \
    for (int p = 0; p < 4; p++) {                                               \
        int id = tid + THREADS * p;                                             \
        int row = id >> 5, ch = id & 31;                                        \
        int n = nn0 + row;                                                      \
        cp16(sx_u32 + ((((row << 7)) + ((ch << 2) ^ ((row & 7) << 4))) << 2),   \
             nodes + (size_t)(n < NTOT ? n : 0) * 128 + ch * 4,                 \
             n < NTOT ? 16 : 0);                                                \
    }                                                                           \
} while (0)

#define ISSUE_M(tile) do {                                                      \
    const int nn0 = (tile) * CT;                                                \
    _Pragma("unroll")                                                           \
    for (int p = 0; p < 4; p++) {                                               \
        int id = tid + THREADS * p;                                             \
        int b = id >> 4, ch = id & 15;                                          \
        int ok = (nn0 + ch * 4) < NTOT;                                         \
        cp16(smm_u32 + (((b << 6) + ((ch ^ (b & 7)) << 2)) << 2),               \
             masks + (size_t)b * NTOT + (ok ? nn0 + ch * 4 : 0), ok ? 16 : 0);  \
    }                                                                           \
} while (0)

// epilogue (R7, unchanged): y = (d+bt)*sigmoid(g+bg), tf32(rna) -> Y[m][n]
#define EPILOGUE() do {                                                         \
    _Pragma("unroll")                                                           \
    for (int s = 0; s < 2; s++)                                                 \
    _Pragma("unroll")                                                           \
    for (int j = 0; j < 2; j++)                                                 \
    _Pragma("unroll")                                                           \
    for (int r = 0; r < 4; r++) {                                               \
        int r1 = r & 1, r2 = r >> 1;                                            \
        int m = mbase + 16 * s + 8 * r2 + gid;                                  \
        int n = nb + 8 * j + 2 * tg + r1;                                       \
        float d  = aD[s][j][r] + btv[j][r1];                                    \
        float gl = aG[s][j][r] + bgv[j][r1];                                    \
        float y = d / (1.0f + __expf(-gl));                                     \
        sY[(m << 7) + (n ^ swc)] = cvt_tf32_f(y);                               \
    }                                                                           \
} while (0)

extern "C" __global__ void __launch_bounds__(THREADS, 1)
agg_kernel(const float* __restrict__ nodes, const int* __restrict__ masks,
           const float* __restrict__ Wt, const float* __restrict__ bt,
           const float* __restrict__ Wg, const float* __restrict__ bg,
           float* __restrict__ out) {
    extern __shared__ float sm[];
    float* sWt = sm + OFF_WT;
    float* sWg = sm + OFF_WG;
    int*   sM  = (int*)(sm + OFF_M);
    float* sY  = sm + OFF_Y;

    const uint32_t smem_u32 = (uint32_t)__cvta_generic_to_shared(sm);
    const uint32_t sx_u32  = smem_u32 + OFF_X * 4;
    const uint32_t smm_u32 = smem_u32 + OFF_M * 4;

    const int tid  = threadIdx.x;
    const int warp = tid >> 5;
    const int lane = tid & 31;
    const int tg   = lane & 3;
    const int gid  = lane >> 2;
    const int stride = gridDim.x;

    // phase A mapping: 32m x 16n per warp (both W matrices)
    const int mbase = (warp & 1) << 5;
    const int nb    = (warp >> 1) << 4;
    // phase B mapping: 32b x 32d per warp
    const int pb = warp & 3;
    const int pd = warp >> 2;
    const int brow0 = (pb << 5) + gid;
    const int msw = gid << 2;
    const int swc = ((gid & 3) << 3) | ((gid & 4) >> 2);

    // per-thread byte bases for phase A
    const uint32_t xbase  = sx_u32 + ((uint32_t)(mbase + gid) << 9);
    const uint32_t wtbase = smem_u32 + OFF_WT * 4 + ((uint32_t)(nb + gid) << 9);
    const uint32_t wgbase = smem_u32 + OFF_WG * 4 + ((uint32_t)(nb + gid) << 9);

    int t = blockIdx.x;          // always < NTILES (148 <= 7813)

    // prologue: start X(t) streaming first
    ISSUE_X(t);
    CP_COMMIT();

    // W^T + bias (once); W pre-rounded rna, stored transposed [n][k]
    for (int i = tid; i < 128 * 128; i += THREADS) {
        int k = i >> 7, n = i & 127;             // gmem: Wt[k*128+n] (coalesced)
        int idx = (n << 7) + (k ^ ((n & 7) << 4));
        sWt[idx] = cvt_tf32_f(Wt[i]);
        sWg[idx] = cvt_tf32_f(Wg[i]);
    }
    float btv[2][2], bgv[2][2];
#pragma unroll
    for (int j = 0; j < 2; j++)
#pragma unroll
        for (int r1 = 0; r1 < 2; r1++) {
            int n = nb + 8 * j + 2 * tg + r1;
            btv[j][r1] = bt[n];
            bgv[j][r1] = bg[n];
        }

    float pc[2][4][4];
#pragma unroll
    for (int s = 0; s < 2; s++)
#pragma unroll
        for (int j = 0; j < 4; j++)
#pragma unroll
            for (int r = 0; r < 4; r++) pc[s][j][r] = 0.0f;

    float aD[2][2][4], aG[2][2][4];

    // ================= peeled first tile: GEMM only =================
    {
        CP_WAIT0();
        __syncthreads();     // X(t) + W visible
#pragma unroll
        for (int s = 0; s < 2; s++)
#pragma unroll
            for (int j = 0; j < 2; j++)
#pragma unroll
                for (int r = 0; r < 4; r++) { aD[s][j][r] = 0.0f; aG[s][j][r] = 0.0f; }
#pragma unroll 2
        for (int ks2 = 0; ks2 < 8; ks2++) ASTEP2(ks2);
        __syncthreads();     // all done reading sX
        if (t + stride < NTILES) ISSUE_X(t + stride);
        ISSUE_M(t);
        CP_COMMIT();
        EPILOGUE();          // writes Y(t)
        t += stride;
    }

    // ================= fused main loop: GEMM(t) + pool(t-1) =================
    for (; t < NTILES; t += stride) {
        CP_WAIT0();          // X(t), M(t-1) landed
        __syncthreads();     // + Y(t-1) visible
#pragma unroll
        for (int s = 0; s < 2; s++)
#pragma unroll
            for (int j = 0; j < 2; j++)
#pragma unroll
                for (int r = 0; r < 4; r++) { aD[s][j][r] = 0.0f; aG[s][j][r] = 0.0f; }
#pragma unroll 2
        for (int ks2 = 0; ks2 < 8; ks2++) {
            ASTEP2(ks2);
            BSTEP(ks2);
        }
        __syncthreads();     // all done reading sX, sM, sY
        if (t + stride < NTILES) ISSUE_X(t + stride);
        ISSUE_M(t);
        CP_COMMIT();
        EPILOGUE();          // writes Y(t)
    }

    // ================= drain: pool for the last processed tile =================
    CP_WAIT0();
    __syncthreads();         // M(last) + Y(last) visible
#pragma unroll 4
    for (int ks = 0; ks < 8; ks++) BSTEP(ks);

    // final reduction: one atomicAdd per pooled element per CTA
#pragma unroll
    for (int s = 0; s < 2; s++)
#pragma unroll
        for (int j = 0; j < 4; j++)
#pragma unroll
            for (int r = 0; r < 4; r++) {
                int b = (pb << 5) + 16 * s + 8 * (r >> 1) + gid;
                int c = (pd << 5) + 8 * j + 2 * tg + (r & 1);
                atomicAdd(&out[b * 128 + c], pc[s][j][r]);
            }
}

extern "C" void kernel_launch(void* const* d_in, const int* in_sizes, int n_in,
                              void* d_out, int out_size) {
    (void)in_sizes; (void)n_in; (void)out_size;
    cudaFuncSetAttribute(agg_kernel, cudaFuncAttributeMaxDynamicSharedMemorySize, SMEM_BYTES);
    zero_out_kernel<<<32, 512>>>((float*)d_out);
    agg_kernel<<<148, THREADS, SMEM_BYTES>>>(
        (const float*)d_in[0], (const int*)d_in[1], (const float*)d_in[2],
        (const float*)d_in[3], (const float*)d_in[4], (const float*)d_in[5], (float*)d_out);
}

// round 12
// speedup vs baseline: 1.1564x; 1.1564x over previous
#include <cuda_runtime.h>
#include <cstdint>

#define NTOT 500000
#define CT 64
#define THREADS 512
#define NTILES ((NTOT + CT - 1) / CT)   // 7813

// smem layout (float offsets)
#define OFF_WT 0        // W^T: [128 n][128 k], word k ^ ((n&3)<<3)   (512B rows)
#define OFF_WG 16384
#define OFF_X  32768    // X:   [64 m][128 k], word k ^ ((m&3)<<3)    (512B rows)
#define OFF_M  40960    // mask:[128 b][64 k] int, word k ^ ((b&7)<<2) (256B rows)
#define OFF_Y  49152    // Y:   [64 m][128 n], word n ^ (((m&3)<<3)|((m&4)>>2))
#define SMEM_FLOATS 57344
#define SMEM_BYTES (SMEM_FLOATS * 4)    // 229376 <= 232448

__device__ __forceinline__ float cvt_tf32_f(float x) {
    uint32_t u; asm("cvt.rna.tf32.f32 %0, %1;" : "=r"(u) : "f"(x));
    return __uint_as_float(u);
}
__device__ __forceinline__ void mma8(float* c,
                                     uint32_t a0, uint32_t a1, uint32_t a2, uint32_t a3,
                                     uint32_t b0, uint32_t b1) {
    asm volatile(
        "mma.sync.aligned.m16n8k8.row.col.f32.tf32.tf32.f32 "
        "{%0,%1,%2,%3}, {%4,%5,%6,%7}, {%8,%9}, {%0,%1,%2,%3};"
        : "+f"(c[0]), "+f"(c[1]), "+f"(c[2]), "+f"(c[3])
        : "r"(a0), "r"(a1), "r"(a2), "r"(a3), "r"(b0), "r"(b1));
}
__device__ __forceinline__ void cp16(uint32_t saddr, const void* g, int szbytes) {
    asm volatile("cp.async.cg.shared.global [%0], [%1], 16, %2;"
                 :: "r"(saddr), "l"(g), "r"(szbytes));
}
#define CP_COMMIT() asm volatile("cp.async.commit_group;")
#define CP_WAIT0()  asm volatile("cp.async.wait_group 0;")
#define LDS64(lo, hi, a) asm volatile("ld.shared.v2.u32 {%0,%1}, [%2];" \
    : "=r"(lo), "=r"(hi) : "r"(a))

extern "C" __global__ void zero_out_kernel(float* __restrict__ out) {
    int i = blockIdx.x * blockDim.x + threadIdx.x;
    if (i < 128 * 128) out[i] = 0.0f;
}

// ---- phase A k-step: 8 LDS.64 -> 8 MMAs.
//   k-relabel: frag slots (tg, tg+4) hold real k (8ks+2tg, 8ks+2tg+1).
//   A (X) and B (W) both relabeled -> dot product unchanged.
//   Swizzle key 8-word granular: (row&3)<<3; 16-lane phase = 4 gid values
//   -> 4 disjoint 8-word windows x 4 tg pairs = 32 banks, conflict-free.
#define ASTEP(ks) do {                                                          \
    const uint32_t koff = (((((ks) << 3) + (tg << 1)) ^ xk) << 2);              \
    uint32_t a0,a1,a2,a3,a4,a5,a6,a7;                                           \
    LDS64(a0, a2, xbase + koff);                                                \
    LDS64(a1, a3, xbase + (8 << 9) + koff);                                     \
    LDS64(a4, a6, xbase + (16 << 9) + koff);                                    \
    LDS64(a5, a7, xbase + (24 << 9) + koff);                                    \
    _Pragma("unroll")                                                           \
    for (int j = 0; j < 2; j++) {                                               \
        uint32_t d0, d1, g0, g1;                                                \
        LDS64(d0, d1, wtbase + (j << 12) + koff);                               \
        LDS64(g0, g1, wgbase + (j << 12) + koff);                               \
        mma8(aD[0][j], a0, a1, a2, a3, d0, d1);                                 \
        mma8(aD[1][j], a4, a5, a6, a7, d0, d1);                                 \
        mma8(aG[0][j], a0, a1, a2, a3, g0, g1);                                 \
        mma8(aG[1][j], a4, a5, a6, a7, g0, g1);                                 \
    }                                                                           \
} while (0)

// ---- phase B k-step (R7 proven, unchanged): LDS.32, natural slots ----
#define BSTEP(ks) do {                                                          \
    const int kk = (ks) * 8 + tg;                                               \
    uint32_t m0 = __float_as_uint((float)sM[(brow0 << 6)        + (kk ^ msw)]); \
    uint32_t m1 = __float_as_uint((float)sM[((brow0 + 8) << 6)  + (kk ^ msw)]); \
    uint32_t m2 = __float_as_uint((float)sM[(brow0 << 6)        + ((kk + 4) ^ msw)]); \
    uint32_t m3 = __float_as_uint((float)sM[((brow0 + 8) << 6)  + ((kk + 4) ^ msw)]); \
    uint32_t m4 = __float_as_uint((float)sM[((brow0 + 16) << 6) + (kk ^ msw)]); \
    uint32_t m5 = __float_as_uint((float)sM[((brow0 + 24) << 6) + (kk ^ msw)]); \
    uint32_t m6 = __float_as_uint((float)sM[((brow0 + 16) << 6) + ((kk + 4) ^ msw)]); \
    uint32_t m7 = __float_as_uint((float)sM[((brow0 + 24) << 6) + ((kk + 4) ^ msw)]); \
    const int yb0 = kk << 7;                                                    \
    const int yb1 = (kk + 4) << 7;                                              \
    const int ysw0 = tg << 3;                                                   \
    const int ysw1 = (tg << 3) | 1;                                             \
    _Pragma("unroll")                                                           \
    for (int j = 0; j < 4; j++) {                                               \
        const int d = (pd << 5) + 8 * j + gid;                                  \
        uint32_t y0 = __float_as_uint(sY[yb0 + (d ^ ysw0)]);                    \
        uint32_t y1 = __float_as_uint(sY[yb1 + (d ^ ysw1)]);                    \
        mma8(pc[0][j], m0, m1, m2, m3, y0, y1);                                 \
        mma8(pc[1][j], m4, m5, m6, m7, y0, y1);                                 \
    }                                                                           \
} while (0)

#define ISSUE_X(tile) do {                                                      \
    const int nn0 = (tile) * CT;                                                \
    _Pragma("unroll")                                                           \
    for (int p = 0; p < 4; p++) {                                               \
        int id = tid + THREADS * p;                                             \
        int row = id >> 5, ch = id & 31;                                        \
        int n = nn0 + row;                                                      \
        cp16(sx_u32 + (((row << 7) + ((ch << 2) ^ ((row & 3) << 3))) << 2),     \
             nodes + (size_t)(n < NTOT ? n : 0) * 128 + ch * 4,                 \
             n < NTOT ? 16 : 0);                                                \
    }                                                                           \
} while (0)

#define ISSUE_M(tile) do {                                                      \
    const int nn0 = (tile) * CT;                                                \
    _Pragma("unroll")                                                           \
    for (int p = 0; p < 4; p++) {                                               \
        int id = tid + THREADS * p;                                             \
        int b = id >> 4, ch = id & 15;                                          \
        int ok = (nn0 + ch * 4) < NTOT;                                         \
        cp16(smm_u32 + (((b << 6) + ((ch ^ (b & 7)) << 2)) << 2),               \
             masks + (size_t)b * NTOT + (ok ? nn0 + ch * 4 : 0), ok ? 16 : 0);  \
    }                                                                           \
} while (0)

// epilogue (R7 proven, unchanged): y = (d+bt)*sigmoid(g+bg), tf32(rna) -> Y[m][n]
#define EPILOGUE() do {                                                         \
    _Pragma("unroll")                                                           \
    for (int s = 0; s < 2; s++)                                                 \
    _Pragma("unroll")                                                           \
    for (int j = 0; j < 2; j++)                                                 \
    _Pragma("unroll")                                                           \
    for (int r = 0; r < 4; r++) {                                               \
        int r1 = r & 1, r2 = r >> 1;                                            \
        int m = mbase + 16 * s + 8 * r2 + gid;                                  \
        int n = nb + 8 * j + 2 * tg + r1;                                       \
        float d  = aD[s][j][r] + btv[j][r1];                                    \
        float gl = aG[s][j][r] + bgv[j][r1];                                    \
        float y = d / (1.0f + __expf(-gl));                                     \
        sY[(m << 7) + (n ^ swc)] = cvt_tf32_f(y);                               \
    }                                                                           \
} while (0)

extern "C" __global__ void __launch_bounds__(THREADS, 1)
agg_kernel(const float* __restrict__ nodes, const int* __restrict__ masks,
           const float* __restrict__ Wt, const float* __restrict__ bt,
           const float* __restrict__ Wg, const float* __restrict__ bg,
           float* __restrict__ out) {
    extern __shared__ float sm[];
    float* sWt = sm + OFF_WT;
    float* sWg = sm + OFF_WG;
    int*   sM  = (int*)(sm + OFF_M);
    float* sY  = sm + OFF_Y;

    const uint32_t smem_u32 = (uint32_t)__cvta_generic_to_shared(sm);
    const uint32_t sx_u32  = smem_u32 + OFF_X * 4;
    const uint32_t smm_u32 = smem_u32 + OFF_M * 4;

    const int tid  = threadIdx.x;
    const int warp = tid >> 5;
    const int lane = tid & 31;
    const int tg   = lane & 3;
    const int gid  = lane >> 2;
    const int stride = gridDim.x;

    // phase A mapping: 32m x 16n per warp (both W matrices)
    const int mbase = (warp & 1) << 5;
    const int nb    = (warp >> 1) << 4;
    // phase B mapping: 32b x 32d per warp
    const int pb = warp & 3;
    const int pd = warp >> 2;
    const int brow0 = (pb << 5) + gid;
    const int msw = gid << 2;
    const int swc = ((gid & 3) << 3) | ((gid & 4) >> 2);

    // phase A per-thread constants
    const uint32_t xk = (uint32_t)(gid & 3) << 3;   // shared 8-word swizzle key
    const uint32_t xbase  = sx_u32 + ((uint32_t)(mbase + gid) << 9);
    const uint32_t wtbase = smem_u32 + OFF_WT * 4 + ((uint32_t)(nb + gid) << 9);
    const uint32_t wgbase = smem_u32 + OFF_WG * 4 + ((uint32_t)(nb + gid) << 9);

    int t = blockIdx.x;          // always < NTILES (148 <= 7813)

    // prologue: start X(t) streaming first
    ISSUE_X(t);
    CP_COMMIT();

    // W^T + bias (once); W pre-rounded rna, stored transposed [n][k]
    for (int i = tid; i < 128 * 128; i += THREADS) {
        int k = i >> 7, n = i & 127;             // gmem: Wt[k*128+n] (coalesced)
        int idx = (n << 7) + (k ^ ((n & 3) << 3));
        sWt[idx] = cvt_tf32_f(Wt[i]);
        sWg[idx] = cvt_tf32_f(Wg[i]);
    }
    float btv[2][2], bgv[2][2];
#pragma unroll
    for (int j = 0; j < 2; j++)
#pragma unroll
        for (int r1 = 0; r1 < 2; r1++) {
            int n = nb + 8 * j + 2 * tg + r1;
            btv[j][r1] = bt[n];
            bgv[j][r1] = bg[n];
        }

    float pc[2][4][4];
#pragma unroll
    for (int s = 0; s < 2; s++)
#pragma unroll
        for (int j = 0; j < 4; j++)
#pragma unroll
            for (int r = 0; r < 4; r++) pc[s][j][r] = 0.0f;

    float aD[2][2][4], aG[2][2][4];

    // ================= peeled first tile: GEMM only =================
    {
        CP_WAIT0();
        __syncthreads();     // X(t) + W visible
#pragma unroll
        for (int s = 0; s < 2; s++)
#pragma unroll
            for (int j = 0; j < 2; j++)
#pragma unroll
                for (int r = 0; r < 4; r++) { aD[s][j][r] = 0.0f; aG[s][j][r] = 0.0f; }
#pragma unroll 4
        for (int ks = 0; ks < 16; ks++) ASTEP(ks);
        __syncthreads();     // all done reading sX
        if (t + stride < NTILES) ISSUE_X(t + stride);
        ISSUE_M(t);
        CP_COMMIT();
        EPILOGUE();          // writes Y(t)
        t += stride;
    }

    // ================= fused main loop: GEMM(t) + pool(t-1) =================
    for (; t < NTILES; t += stride) {
        CP_WAIT0();          // X(t), M(t-1) landed
        __syncthreads();     // + Y(t-1) visible
#pragma unroll
        for (int s = 0; s < 2; s++)
#pragma unroll
            for (int j = 0; j < 2; j++)
#pragma unroll
                for (int r = 0; r < 4; r++) { aD[s][j][r] = 0.0f; aG[s][j][r] = 0.0f; }
#pragma unroll 2
        for (int k8 = 0; k8 < 8; k8++) {
            ASTEP(2 * k8);
            ASTEP(2 * k8 + 1);
            BSTEP(k8);
        }
        __syncthreads();     // all done reading sX, sM, sY
        if (t + stride < NTILES) ISSUE_X(t + stride);
        ISSUE_M(t);
        CP_COMMIT();
        EPILOGUE();          // writes Y(t)
    }

    // ================= drain: pool for the last processed tile =================
    CP_WAIT0();
    __syncthreads();         // M(last) + Y(last) visible
#pragma unroll 4
    for (int ks = 0; ks < 8; ks++) BSTEP(ks);

    // final reduction: one atomicAdd per pooled element per CTA
#pragma unroll
    for (int s = 0; s < 2; s++)
#pragma unroll
        for (int j = 0; j < 4; j++)
#pragma unroll
            for (int r = 0; r < 4; r++) {
                int b = (pb << 5) + 16 * s + 8 * (r >> 1) + gid;
                int c = (pd << 5) + 8 * j + 2 * tg + (r & 1);
                atomicAdd(&out[b * 128 + c], pc[s][j][r]);
            }
}

extern "C" void kernel_launch(void* const* d_in, const int* in_sizes, int n_in,
                              void* d_out, int out_size) {
    (void)in_sizes; (void)n_in; (void)out_size;
    cudaFuncSetAttribute(agg_kernel, cudaFuncAttributeMaxDynamicSharedMemorySize, SMEM_BYTES);
    zero_out_kernel<<<32, 512>>>((float*)d_out);
    agg_kernel<<<148, THREADS, SMEM_BYTES>>>(
        (const float*)d_in[0], (const int*)d_in[1], (const float*)d_in[2],
        (const float*)d_in[3], (const float*)d_in[4], (const float*)d_in[5], (float*)d_out);
}

// round 13
// speedup vs baseline: 1.1599x; 1.0030x over previous
#include <cuda_runtime.h>
#include <cstdint>

#define NTOT 500000
#define CT 64
#define THREADS 512
#define NTILES ((NTOT + CT - 1) / CT)   // 7813

// smem layout (float offsets)
#define OFF_WT 0        // W^T: [128 n][128 k], word k ^ ((n&3)<<3)   (512B rows)
#define OFF_WG 16384
#define OFF_X  32768    // X:   [64 m][128 k], word k ^ ((m&3)<<3)    (512B rows)
#define OFF_M  40960    // mask:[128 b][64 k] int, word k ^ ((b&7)<<2) (256B rows)
#define OFF_Y  49152    // Y:   [64 m][128 n], word n ^ (((m&3)<<3)|((m&4)>>2))
#define SMEM_FLOATS 57344
#define SMEM_BYTES (SMEM_FLOATS * 4)    // 229376 <= 232448

__device__ __forceinline__ float cvt_tf32_f(float x) {
    uint32_t u; asm("cvt.rna.tf32.f32 %0, %1;" : "=r"(u) : "f"(x));
    return __uint_as_float(u);
}
__device__ __forceinline__ void mma8(float* c,
                                     uint32_t a0, uint32_t a1, uint32_t a2, uint32_t a3,
                                     uint32_t b0, uint32_t b1) {
    asm volatile(
        "mma.sync.aligned.m16n8k8.row.col.f32.tf32.tf32.f32 "
        "{%0,%1,%2,%3}, {%4,%5,%6,%7}, {%8,%9}, {%0,%1,%2,%3};"
        : "+f"(c[0]), "+f"(c[1]), "+f"(c[2]), "+f"(c[3])
        : "r"(a0), "r"(a1), "r"(a2), "r"(a3), "r"(b0), "r"(b1));
}
__device__ __forceinline__ void cp16(uint32_t saddr, const void* g, int szbytes) {
    asm volatile("cp.async.cg.shared.global [%0], [%1], 16, %2;"
                 :: "r"(saddr), "l"(g), "r"(szbytes));
}
#define CP_COMMIT() asm volatile("cp.async.commit_group;")
#define CP_WAIT0()  asm volatile("cp.async.wait_group 0;")
#define LDS64(lo, hi, a) asm volatile("ld.shared.v2.u32 {%0,%1}, [%2];" \
    : "=r"(lo), "=r"(hi) : "r"(a))

extern "C" __global__ void zero_out_kernel(float* __restrict__ out) {
    int i = blockIdx.x * blockDim.x + threadIdx.x;
    if (i < 128 * 128) out[i] = 0.0f;
}

// ---- phase A k-step: 8 LDS.64 -> 8 MMAs.
//   k-relabel: frag slots (tg, tg+4) hold real k (8ks+2tg, 8ks+2tg+1).
//   A (X) and B (W) both relabeled -> dot product unchanged.
//   Swizzle key 8-word granular: (row&3)<<3; 16-lane phase = 4 gid values
//   -> 4 disjoint 8-word windows x 4 tg pairs = 32 banks, conflict-free.
#define ASTEP(ks) do {                                                          \
    const uint32_t koff = (((((ks) << 3) + (tg << 1)) ^ xk) << 2);              \
    uint32_t a0,a1,a2,a3,a4,a5,a6,a7;                                           \
    LDS64(a0, a2, xbase + koff);                                                \
    LDS64(a1, a3, xbase + (8 << 9) + koff);                                     \
    LDS64(a4, a6, xbase + (16 << 9) + koff);                                    \
    LDS64(a5, a7, xbase + (24 << 9) + koff);                                    \
    _Pragma("unroll")                                                           \
    for (int j = 0; j < 2; j++) {                                               \
        uint32_t d0, d1, g0, g1;                                                \
        LDS64(d0, d1, wtbase + (j << 12) + koff);                               \
        LDS64(g0, g1, wgbase + (j << 12) + koff);                               \
        mma8(aD[0][j], a0, a1, a2, a3, d0, d1);                                 \
        mma8(aD[1][j], a4, a5, a6, a7, d0, d1);                                 \
        mma8(aG[0][j], a0, a1, a2, a3, g0, g1);                                 \
        mma8(aG[1][j], a4, a5, a6, a7, g0, g1);                                 \
    }                                                                           \
} while (0)

// ---- phase B k-step (R7 proven, unchanged): LDS.32, natural slots ----
#define BSTEP(ks) do {                                                          \
    const int kk = (ks) * 8 + tg;                                               \
    uint32_t m0 = __float_as_uint((float)sM[(brow0 << 6)        + (kk ^ msw)]); \
    uint32_t m1 = __float_as_uint((float)sM[((brow0 + 8) << 6)  + (kk ^ msw)]); \
    uint32_t m2 = __float_as_uint((float)sM[(brow0 << 6)        + ((kk + 4) ^ msw)]); \
    uint32_t m3 = __float_as_uint((float)sM[((brow0 + 8) << 6)  + ((kk + 4) ^ msw)]); \
    uint32_t m4 = __float_as_uint((float)sM[((brow0 + 16) << 6) + (kk ^ msw)]); \
    uint32_t m5 = __float_as_uint((float)sM[((brow0 + 24) << 6) + (kk ^ msw)]); \
    uint32_t m6 = __float_as_uint((float)sM[((brow0 + 16) << 6) + ((kk + 4) ^ msw)]); \
    uint32_t m7 = __float_as_uint((float)sM[((brow0 + 24) << 6) + ((kk + 4) ^ msw)]); \
    const int yb0 = kk << 7;                                                    \
    const int yb1 = (kk + 4) << 7;                                              \
    const int ysw0 = tg << 3;                                                   \
    const int ysw1 = (tg << 3) | 1;                                             \
    _Pragma("unroll")                                                           \
    for (int j = 0; j < 4; j++) {                                               \
        const int d = (pd << 5) + 8 * j + gid;                                  \
        uint32_t y0 = __float_as_uint(sY[yb0 + (d ^ ysw0)]);                    \
        uint32_t y1 = __float_as_uint(sY[yb1 + (d ^ ysw1)]);                    \
        mma8(pc[0][j], m0, m1, m2, m3, y0, y1);                                 \
        mma8(pc[1][j], m4, m5, m6, m7, y0, y1);                                 \
    }                                                                           \
} while (0)

#define ISSUE_X(tile) do {                                                      \
    const int nn0 = (tile) * CT;                                                \
    _Pragma("unroll")                                                           \
    for (int p = 0; p < 4; p++) {                                               \
        int id = tid + THREADS * p;                                             \
        int row = id >> 5, ch = id & 31;                                        \
        int n = nn0 + row;                                                      \
        cp16(sx_u32 + (((row << 7) + ((ch << 2) ^ ((row & 3) << 3))) << 2),     \
             nodes + (size_t)(n < NTOT ? n : 0) * 128 + ch * 4,                 \
             n < NTOT ? 16 : 0);                                                \
    }                                                                           \
} while (0)

#define ISSUE_M(tile) do {                                                      \
    const int nn0 = (tile) * CT;                                                \
    _Pragma("unroll")                                                           \
    for (int p = 0; p < 4; p++) {                                               \
        int id = tid + THREADS * p;                                             \
        int b = id >> 4, ch = id & 15;                                          \
        int ok = (nn0 + ch * 4) < NTOT;                                         \
        cp16(smm_u32 + (((b << 6) + ((ch ^ (b & 7)) << 2)) << 2),               \
             masks + (size_t)b * NTOT + (ok ? nn0 + ch * 4 : 0), ok ? 16 : 0);  \
    }                                                                           \
} while (0)

// epilogue (R7 proven, unchanged): y = (d+bt)*sigmoid(g+bg), tf32(rna) -> Y[m][n]
#define EPILOGUE() do {                                                         \
    _Pragma("unroll")                                                           \
    for (int s = 0; s < 2; s++)                                                 \
    _Pragma("unroll")                                                           \
    for (int j = 0; j < 2; j++)                                                 \
    _Pragma("unroll")                                                           \
    for (int r = 0; r < 4; r++) {                                               \
        int r1 = r & 1, r2 = r >> 1;                                            \
        int m = mbase + 16 * s + 8 * r2 + gid;                                  \
        int n = nb + 8 * j + 2 * tg + r1;                                       \
        float d  = aD[s][j][r] + btv[j][r1];                                    \
        float gl = aG[s][j][r] + bgv[j][r1];                                    \
        float y = d / (1.0f + __expf(-gl));                                     \
        sY[(m << 7) + (n ^ swc)] = cvt_tf32_f(y);                               \
    }                                                                           \
} while (0)

extern "C" __global__ void __launch_bounds__(THREADS, 1)
agg_kernel(const float* __restrict__ nodes, const int* __restrict__ masks,
           const float* __restrict__ Wt, const float* __restrict__ bt,
           const float* __restrict__ Wg, const float* __restrict__ bg,
           float* __restrict__ out) {
    extern __shared__ float sm[];
    float* sWt = sm + OFF_WT;
    float* sWg = sm + OFF_WG;
    int*   sM  = (int*)(sm + OFF_M);
    float* sY  = sm + OFF_Y;

    const uint32_t smem_u32 = (uint32_t)__cvta_generic_to_shared(sm);
    const uint32_t sx_u32  = smem_u32 + OFF_X * 4;
    const uint32_t smm_u32 = smem_u32 + OFF_M * 4;

    const int tid  = threadIdx.x;
    const int warp = tid >> 5;
    const int lane = tid & 31;
    const int tg   = lane & 3;
    const int gid  = lane >> 2;
    const int stride = gridDim.x;

    // phase A mapping: 32m x 16n per warp (both W matrices)
    const int mbase = (warp & 1) << 5;
    const int nb    = (warp >> 1) << 4;
    // phase B mapping: 32b x 32d per warp
    const int pb = warp & 3;
    const int pd = warp >> 2;
    const int brow0 = (pb << 5) + gid;
    const int msw = gid << 2;
    const int swc = ((gid & 3) << 3) | ((gid & 4) >> 2);

    // phase A per-thread constants
    const uint32_t xk = (uint32_t)(gid & 3) << 3;   // shared 8-word swizzle key
    const uint32_t xbase  = sx_u32 + ((uint32_t)(mbase + gid) << 9);
    const uint32_t wtbase = smem_u32 + OFF_WT * 4 + ((uint32_t)(nb + gid) << 9);
    const uint32_t wgbase = smem_u32 + OFF_WG * 4 + ((uint32_t)(nb + gid) << 9);

    int t = blockIdx.x;          // always < NTILES (148 <= 7813)

    // prologue: start X(t) streaming first
    ISSUE_X(t);
    CP_COMMIT();

    // W^T + bias (once); W pre-rounded rna, stored transposed [n][k]
    for (int i = tid; i < 128 * 128; i += THREADS) {
        int k = i >> 7, n = i & 127;             // gmem: Wt[k*128+n] (coalesced)
        int idx = (n << 7) + (k ^ ((n & 3) << 3));
        sWt[idx] = cvt_tf32_f(Wt[i]);
        sWg[idx] = cvt_tf32_f(Wg[i]);
    }
    float btv[2][2], bgv[2][2];
#pragma unroll
    for (int j = 0; j < 2; j++)
#pragma unroll
        for (int r1 = 0; r1 < 2; r1++) {
            int n = nb + 8 * j + 2 * tg + r1;
            btv[j][r1] = bt[n];
            bgv[j][r1] = bg[n];
        }

    float pc[2][4][4];
#pragma unroll
    for (int s = 0; s < 2; s++)
#pragma unroll
        for (int j = 0; j < 4; j++)
#pragma unroll
            for (int r = 0; r < 4; r++) pc[s][j][r] = 0.0f;

    float aD[2][2][4], aG[2][2][4];

    // ================= peeled first tile: GEMM only =================
    {
        CP_WAIT0();
        __syncthreads();     // X(t) + W visible
#pragma unroll
        for (int s = 0; s < 2; s++)
#pragma unroll
            for (int j = 0; j < 2; j++)
#pragma unroll
                for (int r = 0; r < 4; r++) { aD[s][j][r] = 0.0f; aG[s][j][r] = 0.0f; }
#pragma unroll 4
        for (int ks = 0; ks < 16; ks++) ASTEP(ks);
        __syncthreads();     // all done reading sX
        if (t + stride < NTILES) ISSUE_X(t + stride);
        ISSUE_M(t);
        CP_COMMIT();
        EPILOGUE();          // writes Y(t)
        t += stride;
    }

    // ================= fused main loop: GEMM(t) + pool(t-1) =================
    for (; t < NTILES; t += stride) {
        CP_WAIT0();          // X(t), M(t-1) landed
        __syncthreads();     // + Y(t-1) visible
#pragma unroll
        for (int s = 0; s < 2; s++)
#pragma unroll
            for (int j = 0; j < 2; j++)
#pragma unroll
                for (int r = 0; r < 4; r++) { aD[s][j][r] = 0.0f; aG[s][j][r] = 0.0f; }
#pragma unroll 2
        for (int k8 = 0; k8 < 8; k8++) {
            ASTEP(2 * k8);
            ASTEP(2 * k8 + 1);
            BSTEP(k8);
        }
        __syncthreads();     // all done reading sX, sM, sY
        if (t + stride < NTILES) ISSUE_X(t + stride);
        ISSUE_M(t);
        CP_COMMIT();
        EPILOGUE();          // writes Y(t)
    }

    // ================= drain: pool for the last processed tile =================
    CP_WAIT0();
    __syncthreads();         // M(last) + Y(last) visible
#pragma unroll 4
    for (int ks = 0; ks < 8; ks++) BSTEP(ks);

    // final reduction: one atomicAdd per pooled element per CTA
#pragma unroll
    for (int s = 0; s < 2; s++)
#pragma unroll
        for (int j = 0; j < 4; j++)
#pragma unroll
            for (int r = 0; r < 4; r++) {
                int b = (pb << 5) + 16 * s + 8 * (r >> 1) + gid;
                int c = (pd << 5) + 8 * j + 2 * tg + (r & 1);
                atomicAdd(&out[b * 128 + c], pc[s][j][r]);
            }
}

extern "C" void kernel_launch(void* const* d_in, const int* in_sizes, int n_in,
                              void* d_out, int out_size) {
    (void)in_sizes; (void)n_in; (void)out_size;
    cudaFuncSetAttribute(agg_kernel, cudaFuncAttributeMaxDynamicSharedMemorySize, SMEM_BYTES);
    zero_out_kernel<<<32, 512>>>((float*)d_out);
    agg_kernel<<<148, THREADS, SMEM_BYTES>>>(
        (const float*)d_in[0], (const int*)d_in[1], (const float*)d_in[2],
        (const float*)d_in[3], (const float*)d_in[4], (const float*)d_in[5], (float*)d_out);
}

// round 14
// speedup vs baseline: 1.4189x; 1.2233x over previous
#include <cuda_runtime.h>
#include <cstdint>

#define NTOT 500000
#define CT 64
#define THREADS 512
#define NTILES ((NTOT + CT - 1) / CT)

#define OFF_WT16 0
#define OFF_WG16 32768
#define OFF_X16  65536
#define OFF_M16  81920
#define OFF_Y16  98304
#define OFF_XS   114688
#define OFF_MS   147456
#define SMEM_BYTES 180224

__device__ __forceinline__ uint32_t pack_f16x2(float lo, float hi) {
    uint32_t w;
    asm("cvt.rn.f16x2.f32 %0, %1, %2;" : "=r"(w) : "f"(hi), "f"(lo));
    return w;
}
__device__ __forceinline__ void mma16(float* c,
    uint32_t a0, uint32_t a1, uint32_t a2, uint32_t a3, uint32_t b0, uint32_t b1) {
    asm volatile("mma.sync.aligned.m16n8k16.row.col.f32.f16.f16.f32 "
        "{%0,%1,%2,%3}, {%4,%5,%6,%7}, {%8,%9}, {%0,%1,%2,%3};"
        : "+f"(c[0]), "+f"(c[1]), "+f"(c[2]), "+f"(c[3])
        : "r"(a0), "r"(a1), "r"(a2), "r"(a3), "r"(b0), "r"(b1));
}
__device__ __forceinline__ void cp16(uint32_t saddr, const void* g, int sz) {
    asm volatile("cp.async.cg.shared.global [%0], [%1], 16, %2;"
                 :: "r"(saddr), "l"(g), "r"(sz));
}
#define CP_COMMIT() asm volatile("cp.async.commit_group;")
#define CP_WAIT0()  asm volatile("cp.async.wait_group 0;")
#define LDS32(r,a)  asm volatile("ld.shared.u32 %0, [%1];" : "=r"(r) : "r"(a))
#define LDS64F(a0,a1,a) asm volatile("ld.shared.v2.f32 {%0,%1}, [%2];" : "=f"(a0), "=f"(a1) : "r"(a))
#define LDS64U(a0,a1,a) asm volatile("ld.shared.v2.u32 {%0,%1}, [%2];" : "=r"(a0), "=r"(a1) : "r"(a))
#define STS32(a,v) asm volatile("st.shared.u32 [%0], %1;" :: "r"(a), "r"(v))

extern "C" __global__ void zero_out_kernel(float* __restrict__ out) {
    int i = blockIdx.x * blockDim.x + threadIdx.x;
    if (i < 128 * 128) out[i] = 0.0f;
}

#define ISSUE_XS(tile) do { const int nn0 = (tile) * CT;                        \
    _Pragma("unroll") for (int p = 0; p < 4; p++) {                             \
        int id = tid + THREADS * p, row = id >> 5, ch = id & 31;                \
        int n = nn0 + row;                                                      \
        cp16(sxs + (row << 9) + (((uint32_t)(ch ^ (row & 7))) << 4),            \
             nodes + (size_t)(n < NTOT ? n : 0) * 128 + ch * 4,                 \
             n < NTOT ? 16 : 0); } } while (0)

#define ISSUE_MS(tile) do { const int nn0 = (tile) * CT;                        \
    _Pragma("unroll") for (int p = 0; p < 4; p++) {                             \
        int id = tid + THREADS * p, b = id >> 4, ch = id & 15;                  \
        int ok = (nn0 + ch * 4) < NTOT;                                         \
        cp16(sms + (b << 8) + (((uint32_t)(ch ^ (b & 7))) << 4),                \
             masks + (size_t)b * NTOT + (ok ? nn0 + ch * 4 : 0),                \
             ok ? 16 : 0); } } while (0)

#define CONV_X() do {                                                           \
    _Pragma("unroll") for (int i = 0; i < 8; i++) {                             \
        int p = tid + THREADS * i, m = p >> 6, kp = p & 63;                     \
        float f0, f1;                                                           \
        LDS64F(f0, f1, sxs + (m << 9) + ((((kp >> 1) ^ (m & 7))) << 4)          \
                           + ((kp & 1) << 3));                                  \
        STS32(sx16 + (m << 8) + (((uint32_t)(kp ^ ((m & 7) << 2))) << 2),       \
              pack_f16x2(f0, f1)); } } while (0)

#define CONV_M() do {                                                           \
    _Pragma("unroll") for (int i = 0; i < 8; i++) {                             \
        int p = tid + THREADS * i, b = p >> 5, wp = p & 31;                     \
        uint32_t i0, i1;                                                        \
        LDS64U(i0, i1, sms + (b << 8) + ((((wp >> 1) ^ (b & 7))) << 4)          \
                           + ((wp & 1) << 3));                                  \
        STS32(sm16 + (b << 7) + (((uint32_t)(wp ^ ((b & 7) << 2))) << 2),       \
              i0 * 0x3C00u + i1 * 0x3C000000u); } } while (0)

#define ASTEP(ks) do {                                                          \
    const uint32_t w0 = (uint32_t)(((8 * (ks) + tg) ^ xk) << 2);                \
    const uint32_t w1 = (uint32_t)(((8 * (ks) + tg + 4) ^ xk) << 2);            \
    uint32_t a0,a1,a2,a3,a4,a5,a6,a7;                                           \
    LDS32(a0, xrow + w0);          LDS32(a1, xrow + 0x800 + w0);                \
    LDS32(a2, xrow + w1);          LDS32(a3, xrow + 0x800 + w1);                \
    LDS32(a4, xrow + 0x1000 + w0); LDS32(a5, xrow + 0x1800 + w0);               \
    LDS32(a6, xrow + 0x1000 + w1); LDS32(a7, xrow + 0x1800 + w1);               \
    _Pragma("unroll") for (int j = 0; j < 2; j++) {                             \
        uint32_t d0, d1, g0, g1;                                                \
        LDS32(d0, wtb + (j << 11) + w0); LDS32(d1, wtb + (j << 11) + w1);       \
        LDS32(g0, wgb + (j << 11) + w0); LDS32(g1, wgb + (j << 11) + w1);       \
        mma16(aD[0][j], a0, a1, a2, a3, d0, d1);                                \
        mma16(aD[1][j], a4, a5, a6, a7, d0, d1);                                \
        mma16(aG[0][j], a0, a1, a2, a3, g0, g1);                                \
        mma16(aG[1][j], a4, a5, a6, a7, g0, g1); } } while (0)

#define BSTEP(kk) do {                                                          \
    const uint32_t w0 = (uint32_t)(((8 * (kk) + tg) ^ xk) << 2);                \
    const uint32_t w1 = (uint32_t)(((8 * (kk) + tg + 4) ^ xk) << 2);            \
    uint32_t m0,m1,m2,m3,m4,m5,m6,m7;                                           \
    LDS32(m0, mbb + w0);         LDS32(m1, mbb + 0x400 + w0);                   \
    LDS32(m2, mbb + w1);         LDS32(m3, mbb + 0x400 + w1);                   \
    LDS32(m4, mbb + 0x800 + w0); LDS32(m5, mbb + 0xC00 + w0);                   \
    LDS32(m6, mbb + 0x800 + w1); LDS32(m7, mbb + 0xC00 + w1);                   \
    _Pragma("unroll") for (int j = 0; j < 4; j++) {                             \
        uint32_t y0, y1;                                                        \
        LDS32(y0, ybb + (j << 10) + w0); LDS32(y1, ybb + (j << 10) + w1);       \
        mma16(pc[0][j], m0, m1, m2, m3, y0, y1);                                \
        mma16(pc[1][j], m4, m5, m6, m7, y0, y1); } } while (0)

#define EPILOGUE() do {                                                         \
    _Pragma("unroll") for (int s = 0; s < 2; s++)                               \
    _Pragma("unroll") for (int j = 0; j < 2; j++)                               \
    _Pragma("unroll") for (int r = 0; r < 4; r++) {                             \
        int r1 = r & 1, r2 = r >> 1;                                            \
        int m = mbase + 16 * s + 8 * r2 + gid;                                  \
        int n = nb + 8 * j + 2 * tg + r1;                                       \
        float d  = aD[s][j][r] + btv[j][r1];                                    \
        float gl = aG[s][j][r] + bgv[j][r1];                                    \
        float y = d / (1.0f + __expf(-gl));                                     \
        float yp = __shfl_xor_sync(0xffffffffu, y, 4);                          \
        if (!(gid & 1))                                                         \
            STS32(sy16 + (n << 7) +                                             \
                  (((uint32_t)(((m >> 1) ^ ((n & 7) << 2)))) << 2),             \
                  pack_f16x2(y, yp)); } } while (0)

extern "C" __global__ void __launch_bounds__(THREADS, 1)
agg_kernel(const float* __restrict__ nodes, const int* __restrict__ masks,
           const float* __restrict__ Wt, const float* __restrict__ bt,
           const float* __restrict__ Wg, const float* __restrict__ bg,
           float* __restrict__ out) {
    extern __shared__ char smem[];
    const uint32_t sb = (uint32_t)__cvta_generic_to_shared(smem);
    const uint32_t sxs = sb + OFF_XS, sms = sb + OFF_MS;
    const uint32_t sx16 = sb + OFF_X16, sm16 = sb + OFF_M16, sy16 = sb + OFF_Y16;

    const int tid = threadIdx.x, warp = tid >> 5, lane = tid & 31;
    const int tg = lane & 3, gid = lane >> 2;
    const int stride = gridDim.x;
    const int mbase = (warp & 1) << 5;        // A: 32m x 16n x2 mat
    const int nb    = (warp >> 1) << 4;
    const int pb = warp & 3, pd = warp >> 2;  // B: 32b x 32d
    const uint32_t xk = (uint32_t)gid << 2;

    const uint32_t xrow = sx16 + ((uint32_t)(mbase + gid) << 8);
    const uint32_t wtb  = sb + OFF_WT16 + ((uint32_t)(nb + gid) << 8);
    const uint32_t wgb  = sb + OFF_WG16 + ((uint32_t)(nb + gid) << 8);
    const uint32_t mbb  = sm16 + ((uint32_t)((pb << 5) + gid) << 7);
    const uint32_t ybb  = sy16 + ((uint32_t)((pd << 5) + gid) << 7);

    int t = blockIdx.x;
    ISSUE_XS(t);
    CP_COMMIT();

    // W -> f16x2 [n][k-pair], one time
    for (int i = tid; i < 8192; i += THREADS) {
        int n = i & 127, kp = i >> 7;
        uint32_t off = ((uint32_t)n << 8) + (((uint32_t)(kp ^ ((n & 7) << 2))) << 2);
        STS32(sb + OFF_WT16 + off,
              pack_f16x2(Wt[(2 * kp) * 128 + n], Wt[(2 * kp + 1) * 128 + n]));
        STS32(sb + OFF_WG16 + off,
              pack_f16x2(Wg[(2 * kp) * 128 + n], Wg[(2 * kp + 1) * 128 + n]));
    }
    float btv[2][2], bgv[2][2];
#pragma unroll
    for (int j = 0; j < 2; j++)
#pragma unroll
        for (int r1 = 0; r1 < 2; r1++) {
            int n = nb + 8 * j + 2 * tg + r1;
            btv[j][r1] = bt[n]; bgv[j][r1] = bg[n];
        }

    float pc[2][4][4];
#pragma unroll
    for (int s = 0; s < 2; s++)
#pragma unroll
        for (int j = 0; j < 4; j++)
#pragma unroll
            for (int r = 0; r < 4; r++) pc[s][j][r] = 0.0f;
    float aD[2][2][4], aG[2][2][4];

    // peeled first tile: GEMM only
    {
        CP_WAIT0(); __syncthreads();
        CONV_X(); __syncthreads();
#pragma unroll
        for (int s = 0; s < 2; s++)
#pragma unroll
            for (int j = 0; j < 2; j++)
#pragma unroll
                for (int r = 0; r < 4; r++) { aD[s][j][r] = 0.0f; aG[s][j][r] = 0.0f; }
#pragma unroll
        for (int ks = 0; ks < 8; ks++) ASTEP(ks);
        __syncthreads();
        if (t + stride < NTILES) ISSUE_XS(t + stride);
        ISSUE_MS(t); CP_COMMIT();
        EPILOGUE();
        t += stride;
    }

    // fused loop: GEMM(t) + pool(t-1)
    for (; t < NTILES; t += stride) {
        CP_WAIT0(); __syncthreads();      // XS(t), MS(t-1) landed; Y16(t-1) written
        CONV_X(); CONV_M();
        __syncthreads();
#pragma unroll
        for (int s = 0; s < 2; s++)
#pragma unroll
            for (int j = 0; j < 2; j++)
#pragma unroll
                for (int r = 0; r < 4; r++) { aD[s][j][r] = 0.0f; aG[s][j][r] = 0.0f; }
#pragma unroll
        for (int q = 0; q < 4; q++) {
            ASTEP(2 * q); ASTEP(2 * q + 1); BSTEP(q);
        }
        __syncthreads();
        if (t + stride < NTILES) ISSUE_XS(t + stride);
        ISSUE_MS(t); CP_COMMIT();
        EPILOGUE();
    }

    // drain: pool last tile
    CP_WAIT0(); __syncthreads();
    CONV_M(); __syncthreads();
#pragma unroll
    for (int q = 0; q < 4; q++) BSTEP(q);

#pragma unroll
    for (int s = 0; s < 2; s++)
#pragma unroll
        for (int j = 0; j < 4; j++)
#pragma unroll
            for (int r = 0; r < 4; r++) {
                int b = (pb << 5) + 16 * s + 8 * (r >> 1) + gid;
                int c = (pd << 5) + 8 * j + 2 * tg + (r & 1);
                atomicAdd(&out[b * 128 + c], pc[s][j][r]);
            }
}

extern "C" void kernel_launch(void* const* d_in, const int* in_sizes, int n_in,
                              void* d_out, int out_size) {
    (void)in_sizes; (void)n_in; (void)out_size;
    cudaFuncSetAttribute(agg_kernel, cudaFuncAttributeMaxDynamicSharedMemorySize, SMEM_BYTES);
    zero_out_kernel<<<32, 512>>>((float*)d_out);
    agg_kernel<<<148, THREADS, SMEM_BYTES>>>(
        (const float*)d_in[0], (const int*)d_in[1], (const float*)d_in[2],
        (const float*)d_in[3], (const float*)d_in[4], (const float*)d_in[5], (float*)d_out);
}